// round 15
// baseline (speedup 1.0000x reference)
#include <cuda_runtime.h>
#include <math.h>
#include <stdint.h>

#define C 256
#define B 16
#define NWARPS 8
#define THREADS 256
#define NBLOCKS 592          // 4 per SM

typedef unsigned long long u64t;

// Scratch accumulators (device globals; re-zeroed in finalize each replay)
__device__ float g_S1[B * C];
__device__ float g_S2[B * C];
__device__ float g_Z[B];
__device__ float g_W[B];
__device__ float g_mean[C];
__device__ float g_rstd[C];

// ---- packed f32x2 math ----------------------------------------------------
__device__ __forceinline__ u64t fma2(u64t a, u64t b, u64t c) {
    u64t d;
    asm("fma.rn.f32x2 %0, %1, %2, %3;" : "=l"(d) : "l"(a), "l"(b), "l"(c));
    return d;
}
__device__ __forceinline__ u64t mul2(u64t a, u64t b) {
    u64t d;
    asm("mul.rn.f32x2 %0, %1, %2;" : "=l"(d) : "l"(a), "l"(b));
    return d;
}
__device__ __forceinline__ u64t pk2(float lo, float hi) {
    u64t r;
    asm("mov.b64 %0, {%1, %2};" : "=l"(r) : "f"(lo), "f"(hi));
    return r;
}
__device__ __forceinline__ float2 upk2(u64t v) {
    float2 f;
    asm("mov.b64 {%0, %1}, %2;" : "=f"(f.x), "=f"(f.y) : "l"(v));
    return f;
}

// ---------------------------------------------------------------------------
__device__ __forceinline__ void flush_acc(int segv, int lane,
                                          u64t* s1p, u64t* s2p,
                                          float zacc, float wacc) {
    int c0 = lane * 4;
    int c1 = 128 + lane * 4;
    float2 v;
    v = upk2(s1p[0]); atomicAdd(&g_S1[segv*C + c0    ], v.x); atomicAdd(&g_S1[segv*C + c0 + 1], v.y);
    v = upk2(s1p[1]); atomicAdd(&g_S1[segv*C + c0 + 2], v.x); atomicAdd(&g_S1[segv*C + c0 + 3], v.y);
    v = upk2(s1p[2]); atomicAdd(&g_S1[segv*C + c1    ], v.x); atomicAdd(&g_S1[segv*C + c1 + 1], v.y);
    v = upk2(s1p[3]); atomicAdd(&g_S1[segv*C + c1 + 2], v.x); atomicAdd(&g_S1[segv*C + c1 + 3], v.y);
    v = upk2(s2p[0]); atomicAdd(&g_S2[segv*C + c0    ], v.x); atomicAdd(&g_S2[segv*C + c0 + 1], v.y);
    v = upk2(s2p[1]); atomicAdd(&g_S2[segv*C + c0 + 2], v.x); atomicAdd(&g_S2[segv*C + c0 + 3], v.y);
    v = upk2(s2p[2]); atomicAdd(&g_S2[segv*C + c1    ], v.x); atomicAdd(&g_S2[segv*C + c1 + 1], v.y);
    v = upk2(s2p[3]); atomicAdd(&g_S2[segv*C + c1 + 2], v.x); atomicAdd(&g_S2[segv*C + c1 + 3], v.y);
    if (lane == 0) {
        atomicAdd(&g_Z[segv], zacc);
        atomicAdd(&g_W[segv], wacc);
    }
}

// packed dot: 8 channels (4 pairs), two 2-deep chains for ILP
__device__ __forceinline__ float dot_pk(ulonglong2 a0, ulonglong2 a1,
                                        ulonglong2 w0, ulonglong2 w1) {
    u64t p = fma2(a0.x, w0.x, mul2(a0.y, w0.y));
    u64t q = fma2(a1.x, w1.x, mul2(a1.y, w1.y));
    float2 fp = upk2(p), fq = upk2(q);
    return (fp.x + fq.x) + (fp.y + fq.y);
}
// packed moment accumulation for one row (8 channels)
__device__ __forceinline__ void accum_pk(float wr, ulonglong2 a0, ulonglong2 a1,
                                         u64t* s1p, u64t* s2p) {
    u64t wr2 = pk2(wr, wr);
    s1p[0] = fma2(wr2, a0.x, s1p[0]);
    s1p[1] = fma2(wr2, a0.y, s1p[1]);
    s1p[2] = fma2(wr2, a1.x, s1p[2]);
    s1p[3] = fma2(wr2, a1.y, s1p[3]);
    s2p[0] = fma2(wr2, mul2(a0.x, a0.x), s2p[0]);
    s2p[1] = fma2(wr2, mul2(a0.y, a0.y), s2p[1]);
    s2p[2] = fma2(wr2, mul2(a1.x, a1.x), s2p[2]);
    s2p[3] = fma2(wr2, mul2(a1.y, a1.y), s2p[3]);
}

// ---------------------------------------------------------------------------
// pass 1: NO staging — direct streaming LDG (__ldcs) at 4 CTAs/SM (32 warps).
// Warp owns a contiguous row range; per iter: 4 independent LDG.128 (2 rows),
// dots -> 4-chain butterfly -> exp/sigmoid -> packed accumulation.
// Weights re-read from smem each iter to keep register count <= 64.
// ---------------------------------------------------------------------------
__global__ __launch_bounds__(THREADS, 4)
void pass1_kernel(const float* __restrict__ feats,
                  const int*   __restrict__ seg,
                  const float* __restrict__ wl,
                  const float* __restrict__ bl,
                  const float* __restrict__ wg,
                  const float* __restrict__ bg,
                  int n)
{
    __shared__ float4 swl[64];
    __shared__ float4 swg[64];

    int tid  = threadIdx.x;
    int warp = tid >> 5;
    int lane = tid & 31;

    if (tid < 64)        swl[tid]      = ((const float4*)wl)[tid];
    else if (tid < 128)  swg[tid - 64] = ((const float4*)wg)[tid - 64];
    __syncthreads();

    int chunk = (n + NBLOCKS - 1) / NBLOCKS;
    int b0 = blockIdx.x * chunk;
    int b1 = min(n, b0 + chunk);
    if (b0 >= n) return;
    int wchunk = (chunk + NWARPS - 1) / NWARPS;
    int r0 = b0 + warp * wchunk;
    int r1 = min(b1, r0 + wchunk);
    if (r0 >= r1) return;

    float blv = bl[0], bgv = bg[0];

    u64t s1p[4], s2p[4];
#pragma unroll
    for (int k = 0; k < 4; k++) { s1p[k] = 0ull; s2p[k] = 0ull; }
    float zacc = 0.f, wacc = 0.f;
    int cur = -1;

    for (int r = r0; r < r1; r += 2) {
        int rv = min(2, r1 - r);
        const ulonglong2* ra = (const ulonglong2*)(feats + (size_t)r * C);

        // issue all loads up front (independent LDG.128, streaming)
        ulonglong2 xa0 = __ldcs(ra + lane);
        ulonglong2 xa1 = __ldcs(ra + 32 + lane);
        ulonglong2 xb0, xb1;
        if (rv == 2) {
            xb0 = __ldcs(ra + 64 + lane);
            xb1 = __ldcs(ra + 96 + lane);
        }
        int s0 = __ldg(&seg[r]);
        int s1v = (rv == 2) ? __ldg(&seg[r + 1]) : s0;

        // weights from smem (rematerialized each iter; conflict-free LDS.128)
        ulonglong2 wl0 = *(const ulonglong2*)&swl[lane];
        ulonglong2 wl1 = *(const ulonglong2*)&swl[32 + lane];
        ulonglong2 wg0 = *(const ulonglong2*)&swg[lane];
        ulonglong2 wg1 = *(const ulonglong2*)&swg[32 + lane];

        if (s0 == s1v && rv == 2) {
            // ---- fast path: both rows one segment ----
            if (s0 != cur) {
                if (cur >= 0) flush_acc(cur, lane, s1p, s2p, zacc, wacc);
#pragma unroll
                for (int k = 0; k < 4; k++) { s1p[k] = 0ull; s2p[k] = 0ull; }
                zacc = 0.f; wacc = 0.f;
                cur = s0;
            }
            float dla = dot_pk(xa0, xa1, wl0, wl1), dga = dot_pk(xa0, xa1, wg0, wg1);
            float dlb = dot_pk(xb0, xb1, wl0, wl1), dgb = dot_pk(xb0, xb1, wg0, wg1);

            // 4 interleaved butterfly chains
#pragma unroll
            for (int o = 16; o; o >>= 1) {
                dla += __shfl_xor_sync(0xffffffffu, dla, o);
                dga += __shfl_xor_sync(0xffffffffu, dga, o);
                dlb += __shfl_xor_sync(0xffffffffu, dlb, o);
                dgb += __shfl_xor_sync(0xffffffffu, dgb, o);
            }
            float ea = __expf(dga + bgv);
            float eb = __expf(dgb + bgv);
            float wra = __fdividef(ea, 1.0f + __expf(-(dla + blv)));
            float wrb = __fdividef(eb, 1.0f + __expf(-(dlb + blv)));
            zacc += ea + eb;
            wacc += wra + wrb;
            accum_pk(wra, xa0, xa1, s1p, s2p);
            accum_pk(wrb, xb0, xb1, s1p, s2p);
        } else {
            // ---- slow path: boundary pair or single row ----
            // row A
            if (s0 != cur) {
                if (cur >= 0) flush_acc(cur, lane, s1p, s2p, zacc, wacc);
#pragma unroll
                for (int k = 0; k < 4; k++) { s1p[k] = 0ull; s2p[k] = 0ull; }
                zacc = 0.f; wacc = 0.f;
                cur = s0;
            }
            {
                float dl = dot_pk(xa0, xa1, wl0, wl1);
                float dg = dot_pk(xa0, xa1, wg0, wg1);
#pragma unroll
                for (int o = 16; o; o >>= 1) {
                    dl += __shfl_xor_sync(0xffffffffu, dl, o);
                    dg += __shfl_xor_sync(0xffffffffu, dg, o);
                }
                float e  = __expf(dg + bgv);
                float wr = __fdividef(e, 1.0f + __expf(-(dl + blv)));
                zacc += e;
                wacc += wr;
                accum_pk(wr, xa0, xa1, s1p, s2p);
            }
            // row B
            if (rv == 2) {
                if (s1v != cur) {
                    flush_acc(cur, lane, s1p, s2p, zacc, wacc);
#pragma unroll
                    for (int k = 0; k < 4; k++) { s1p[k] = 0ull; s2p[k] = 0ull; }
                    zacc = 0.f; wacc = 0.f;
                    cur = s1v;
                }
                float dl = dot_pk(xb0, xb1, wl0, wl1);
                float dg = dot_pk(xb0, xb1, wg0, wg1);
#pragma unroll
                for (int o = 16; o; o >>= 1) {
                    dl += __shfl_xor_sync(0xffffffffu, dl, o);
                    dg += __shfl_xor_sync(0xffffffffu, dg, o);
                }
                float e  = __expf(dg + bgv);
                float wr = __fdividef(e, 1.0f + __expf(-(dl + blv)));
                zacc += e;
                wacc += wr;
                accum_pk(wr, xb0, xb1, s1p, s2p);
            }
        }
    }
    if (cur >= 0) flush_acc(cur, lane, s1p, s2p, zacc, wacc);
}

// ---------------------------------------------------------------------------
// finalize: fold 16 segments into mean/rstd, then re-zero accumulators
// ---------------------------------------------------------------------------
__global__ void finalize_kernel() {
    __shared__ float invZ[B];
    __shared__ float invU;
    int t = threadIdx.x;
    if (t < B) invZ[t] = 1.0f / g_Z[t];
    __syncthreads();
    if (t == 0) {
        float U = 0.f;
        for (int b = 0; b < B; b++) U += g_W[b] * invZ[b];
        invU = 1.0f / U;
    }
    __syncthreads();
    float m1 = 0.f, m2 = 0.f;
    for (int b = 0; b < B; b++) {
        m1 += g_S1[b * C + t] * invZ[b];
        m2 += g_S2[b * C + t] * invZ[b];
    }
    float iu = invU;
    m1 *= iu;
    m2 *= iu;
    float var = m2 - m1 * m1;   // sum(weight) == 1 exactly in the math
    g_mean[t] = m1;
    g_rstd[t] = 1.0f / sqrtf(var);
    for (int b = 0; b < B; b++) {
        g_S1[b * C + t] = 0.f;
        g_S2[b * C + t] = 0.f;
    }
    if (t < B) { g_Z[t] = 0.f; g_W[t] = 0.f; }
}

// ---------------------------------------------------------------------------
// pass 2: out = (x - mean[c]) * rstd[c]
// ---------------------------------------------------------------------------
__global__ __launch_bounds__(256)
void normalize_kernel(const float* __restrict__ feats,
                      float* __restrict__ out, int total4)
{
    int base = blockIdx.x * 1024 + threadIdx.x;
    if (base >= total4) return;
    const float4* f4 = (const float4*)feats;
    float4*       o4 = (float4*)out;
    const float4* m4 = (const float4*)g_mean;
    const float4* r4 = (const float4*)g_rstd;

    int cf = base & 63;
    float4 m  = m4[cf];
    float4 rs = r4[cf];

#pragma unroll
    for (int k = 0; k < 4; k++) {
        int i = base + k * 256;
        if (i < total4) {
            float4 x = __ldcs(f4 + i);
            float4 y;
            y.x = (x.x - m.x) * rs.x;
            y.y = (x.y - m.y) * rs.y;
            y.z = (x.z - m.z) * rs.z;
            y.w = (x.w - m.w) * rs.w;
            __stcs(o4 + i, y);
        }
    }
}

// ---------------------------------------------------------------------------
extern "C" void kernel_launch(void* const* d_in, const int* in_sizes, int n_in,
                              void* d_out, int out_size) {
    const float* feats = (const float*)d_in[0];
    const int*   seg   = (const int*)  d_in[1];
    const float* wl    = (const float*)d_in[2];
    const float* bl    = (const float*)d_in[3];
    const float* wg    = (const float*)d_in[4];
    const float* bg    = (const float*)d_in[5];
    float*       out   = (float*)d_out;

    int n = in_sizes[0] / C;

    pass1_kernel<<<NBLOCKS, THREADS>>>(feats, seg, wl, bl, wg, bg, n);

    finalize_kernel<<<1, C>>>();

    int total4 = n * (C / 4);
    normalize_kernel<<<(total4 + 1023) / 1024, 256>>>(feats, out, total4);
}

// round 16
// speedup vs baseline: 1.1682x; 1.1682x over previous
#include <cuda_runtime.h>
#include <math.h>
#include <stdint.h>

#define C 256
#define B 16
#define TILE 24              // rows per logical tile; 3 rows per warp
#define RPW 3                // rows per warp-chunk (3 KB)
#define DEPTH 2              // per-warp pipeline stages
#define NWARPS 8
#define THREADS 256
#define NBLOCKS 592          // 4 per SM

#define CHUNK_FLOATS (RPW * C)                    // 768 floats = 3 KB
#define WARP_BUF_FLOATS (DEPTH * CHUNK_FLOATS)    // 6 KB / warp
#define DATA_FLOATS (NWARPS * WARP_BUF_FLOATS)    // 48 KB / CTA
#define SMEM_BYTES (DATA_FLOATS * 4 + NWARPS * DEPTH * 8 + 16)

typedef unsigned long long u64t;

// Scratch accumulators (device globals; re-zeroed in finalize each replay)
__device__ float g_S1[B * C];
__device__ float g_S2[B * C];
__device__ float g_Z[B];
__device__ float g_W[B];
__device__ float g_mean[C];
__device__ float g_rstd[C];

// ---------------------------------------------------------------------------
// PTX helpers
// ---------------------------------------------------------------------------
__device__ __forceinline__ uint32_t smem_u32(const void* p) {
    uint32_t a;
    asm("{ .reg .u64 t; cvta.to.shared.u64 t, %1; cvt.u32.u64 %0, t; }"
        : "=r"(a) : "l"(p));
    return a;
}
__device__ __forceinline__ void mbar_init(uint32_t mbar, uint32_t cnt) {
    asm volatile("mbarrier.init.shared.b64 [%0], %1;" :: "r"(mbar), "r"(cnt) : "memory");
}
__device__ __forceinline__ void mbar_expect_tx(uint32_t mbar, uint32_t bytes) {
    asm volatile("mbarrier.arrive.expect_tx.shared.b64 _, [%0], %1;"
                 :: "r"(mbar), "r"(bytes) : "memory");
}
__device__ __forceinline__ void mbar_arrive(uint32_t mbar) {
    asm volatile("mbarrier.arrive.shared.b64 _, [%0];" :: "r"(mbar) : "memory");
}
__device__ __forceinline__ void bulk_g2s(uint32_t dst, const void* src,
                                         uint32_t bytes, uint32_t mbar) {
    asm volatile(
        "cp.async.bulk.shared::cta.global.mbarrier::complete_tx::bytes [%0], [%1], %2, [%3];"
        :: "r"(dst), "l"(src), "r"(bytes), "r"(mbar) : "memory");
}
__device__ __forceinline__ void mbar_wait(uint32_t mbar, uint32_t parity) {
    uint32_t done;
    asm volatile(
        "{\n\t.reg .pred p;\n\t"
        "mbarrier.try_wait.parity.acquire.cta.shared::cta.b64 p, [%1], %2;\n\t"
        "selp.b32 %0, 1, 0, p;\n\t}"
        : "=r"(done) : "r"(mbar), "r"(parity) : "memory");
    if (!done) {
        asm volatile(
            "{\n\t.reg .pred P1;\n\t"
            "W_%=:\n\t"
            "mbarrier.try_wait.parity.acquire.cta.shared::cta.b64 P1, [%0], %1, 0x989680;\n\t"
            "@P1 bra.uni D_%=;\n\t"
            "bra.uni W_%=;\n\t"
            "D_%=:\n\t}"
            :: "r"(mbar), "r"(parity) : "memory");
    }
}

// ---- packed f32x2 math ----------------------------------------------------
__device__ __forceinline__ u64t fma2(u64t a, u64t b, u64t c) {
    u64t d;
    asm("fma.rn.f32x2 %0, %1, %2, %3;" : "=l"(d) : "l"(a), "l"(b), "l"(c));
    return d;
}
__device__ __forceinline__ u64t mul2(u64t a, u64t b) {
    u64t d;
    asm("mul.rn.f32x2 %0, %1, %2;" : "=l"(d) : "l"(a), "l"(b));
    return d;
}
__device__ __forceinline__ u64t pk2(float lo, float hi) {
    u64t r;
    asm("mov.b64 %0, {%1, %2};" : "=l"(r) : "f"(lo), "f"(hi));
    return r;
}
__device__ __forceinline__ float2 upk2(u64t v) {
    float2 f;
    asm("mov.b64 {%0, %1}, %2;" : "=f"(f.x), "=f"(f.y) : "l"(v));
    return f;
}

// ---------------------------------------------------------------------------
__device__ __forceinline__ void flush_acc(int segv, int lane,
                                          u64t* s1p, u64t* s2p,
                                          float zacc, float wacc) {
    int c0 = lane * 4;
    int c1 = 128 + lane * 4;
    float2 v;
    v = upk2(s1p[0]); atomicAdd(&g_S1[segv*C + c0    ], v.x); atomicAdd(&g_S1[segv*C + c0 + 1], v.y);
    v = upk2(s1p[1]); atomicAdd(&g_S1[segv*C + c0 + 2], v.x); atomicAdd(&g_S1[segv*C + c0 + 3], v.y);
    v = upk2(s1p[2]); atomicAdd(&g_S1[segv*C + c1    ], v.x); atomicAdd(&g_S1[segv*C + c1 + 1], v.y);
    v = upk2(s1p[3]); atomicAdd(&g_S1[segv*C + c1 + 2], v.x); atomicAdd(&g_S1[segv*C + c1 + 3], v.y);
    v = upk2(s2p[0]); atomicAdd(&g_S2[segv*C + c0    ], v.x); atomicAdd(&g_S2[segv*C + c0 + 1], v.y);
    v = upk2(s2p[1]); atomicAdd(&g_S2[segv*C + c0 + 2], v.x); atomicAdd(&g_S2[segv*C + c0 + 3], v.y);
    v = upk2(s2p[2]); atomicAdd(&g_S2[segv*C + c1    ], v.x); atomicAdd(&g_S2[segv*C + c1 + 1], v.y);
    v = upk2(s2p[3]); atomicAdd(&g_S2[segv*C + c1 + 2], v.x); atomicAdd(&g_S2[segv*C + c1 + 3], v.y);
    if (lane == 0) {
        atomicAdd(&g_Z[segv], zacc);
        atomicAdd(&g_W[segv], wacc);
    }
}

// packed dot: 8 channels (4 pairs), two 2-deep chains for ILP
__device__ __forceinline__ float dot_pk(ulonglong2 a0, ulonglong2 a1,
                                        ulonglong2 w0, ulonglong2 w1) {
    u64t p = fma2(a0.x, w0.x, mul2(a0.y, w0.y));
    u64t q = fma2(a1.x, w1.x, mul2(a1.y, w1.y));
    float2 fp = upk2(p), fq = upk2(q);
    return (fp.x + fq.x) + (fp.y + fq.y);
}
// packed moment accumulation for one row (8 channels)
__device__ __forceinline__ void accum_pk(float wr, ulonglong2 a0, ulonglong2 a1,
                                         u64t* s1p, u64t* s2p) {
    u64t wr2 = pk2(wr, wr);
    s1p[0] = fma2(wr2, a0.x, s1p[0]);
    s1p[1] = fma2(wr2, a0.y, s1p[1]);
    s1p[2] = fma2(wr2, a1.x, s1p[2]);
    s1p[3] = fma2(wr2, a1.y, s1p[3]);
    s2p[0] = fma2(wr2, mul2(a0.x, a0.x), s2p[0]);
    s2p[1] = fma2(wr2, mul2(a0.y, a0.y), s2p[1]);
    s2p[2] = fma2(wr2, mul2(a1.x, a1.x), s2p[2]);
    s2p[3] = fma2(wr2, mul2(a1.y, a1.y), s2p[3]);
}

// ---------------------------------------------------------------------------
// pass 1: PER-WARP private TMA pipelines (R13 structure), DEPTH=2 so smem fits
// 4 CTAs/SM; __launch_bounds__(256,4) caps regs at 64.
// ---------------------------------------------------------------------------
extern __shared__ char smem_raw[];

__global__ __launch_bounds__(THREADS, 4)
void pass1_kernel(const float* __restrict__ feats,
                  const int*   __restrict__ seg,
                  const float* __restrict__ wl,
                  const float* __restrict__ bl,
                  const float* __restrict__ wg,
                  const float* __restrict__ bg,
                  int n)
{
    __shared__ float4 swl[64];
    __shared__ float4 swg[64];

    float* data = (float*)smem_raw;
    uint64_t* mbar64 = (uint64_t*)(smem_raw + (size_t)DATA_FLOATS * 4);

    int ntiles = (n + TILE - 1) / TILE;
    int chunk  = (ntiles + NBLOCKS - 1) / NBLOCKS;
    int t0 = blockIdx.x * chunk;
    int t1 = min(ntiles, t0 + chunk);
    int nt = t1 - t0;

    int tid  = threadIdx.x;
    int warp = tid >> 5;
    int lane = tid & 31;

    // weights preload
    if (tid < 64)        swl[tid]      = ((const float4*)wl)[tid];
    else if (tid < 128)  swg[tid - 64] = ((const float4*)wg)[tid - 64];

    // this warp's private ring
    float* wbuf = data + warp * WARP_BUF_FLOATS;
    uint32_t mb[DEPTH], buf_s[DEPTH];
#pragma unroll
    for (int d = 0; d < DEPTH; d++) {
        mb[d]    = smem_u32(&mbar64[warp * DEPTH + d]);
        buf_s[d] = smem_u32(wbuf + d * CHUNK_FLOATS);
    }
    if (lane == 0) {
#pragma unroll
        for (int d = 0; d < DEPTH; d++) mbar_init(mb[d], 1);
    }
    __syncthreads();   // weights visible; warp-local mbars ready

    if (nt <= 0) return;

    // prologue: this warp issues its first DEPTH chunks
    if (lane == 0) {
#pragma unroll
        for (int d = 0; d < DEPTH; d++) {
            if (d < nt) {
                int r0 = (t0 + d) * TILE + warp * RPW;
                int rv = min(RPW, n - r0);
                if (rv > 0) {
                    uint32_t bytes = (uint32_t)rv * C * 4;
                    mbar_expect_tx(mb[d], bytes);
                    bulk_g2s(buf_s[d], feats + (size_t)r0 * C, bytes, mb[d]);
                } else {
                    mbar_arrive(mb[d]);
                }
            } else {
                mbar_arrive(mb[d]);
            }
        }
    }

    float blv = bl[0], bgv = bg[0];

    u64t s1p[4], s2p[4];
#pragma unroll
    for (int k = 0; k < 4; k++) { s1p[k] = 0ull; s2p[k] = 0ull; }
    float zacc = 0.f, wacc = 0.f;
    int cur = -1;

    for (int i = 0; i < nt; i++) {
        int st = i & (DEPTH - 1);
        uint32_t parity = (uint32_t)((i / DEPTH) & 1);
        mbar_wait(mb[st], parity);

        int r0 = (t0 + i) * TILE + warp * RPW;
        int rv = min(RPW, n - r0);

        if (rv > 0) {
            const float* tp = wbuf + st * CHUNK_FLOATS;
            int s_lo = __ldg(&seg[r0]);
            int s_hi = __ldg(&seg[r0 + rv - 1]);

            // weights from smem (rematerialized each chunk, conflict-free LDS)
            ulonglong2 wl0 = *(const ulonglong2*)&swl[lane];
            ulonglong2 wl1 = *(const ulonglong2*)&swl[32 + lane];
            ulonglong2 wg0 = *(const ulonglong2*)&swg[lane];
            ulonglong2 wg1 = *(const ulonglong2*)&swg[32 + lane];

            if (s_lo == s_hi && rv == RPW) {
                // ---- fast path: 3 rows, one segment ----
                if (s_lo != cur) {
                    if (cur >= 0) flush_acc(cur, lane, s1p, s2p, zacc, wacc);
#pragma unroll
                    for (int k = 0; k < 4; k++) { s1p[k] = 0ull; s2p[k] = 0ull; }
                    zacc = 0.f; wacc = 0.f;
                    cur = s_lo;
                }
                const float* rp = tp + lane * 4;
                ulonglong2 xa0 = *(const ulonglong2*)(rp);
                ulonglong2 xa1 = *(const ulonglong2*)(rp + 128);
                ulonglong2 xb0 = *(const ulonglong2*)(rp + C);
                ulonglong2 xb1 = *(const ulonglong2*)(rp + C + 128);
                ulonglong2 xc0 = *(const ulonglong2*)(rp + 2 * C);
                ulonglong2 xc1 = *(const ulonglong2*)(rp + 2 * C + 128);

                float dla = dot_pk(xa0, xa1, wl0, wl1), dga = dot_pk(xa0, xa1, wg0, wg1);
                float dlb = dot_pk(xb0, xb1, wl0, wl1), dgb = dot_pk(xb0, xb1, wg0, wg1);
                float dlc = dot_pk(xc0, xc1, wl0, wl1), dgc = dot_pk(xc0, xc1, wg0, wg1);

                // 6 interleaved butterfly chains
#pragma unroll
                for (int o = 16; o; o >>= 1) {
                    dla += __shfl_xor_sync(0xffffffffu, dla, o);
                    dga += __shfl_xor_sync(0xffffffffu, dga, o);
                    dlb += __shfl_xor_sync(0xffffffffu, dlb, o);
                    dgb += __shfl_xor_sync(0xffffffffu, dgb, o);
                    dlc += __shfl_xor_sync(0xffffffffu, dlc, o);
                    dgc += __shfl_xor_sync(0xffffffffu, dgc, o);
                }
                float ea = __expf(dga + bgv);
                float eb = __expf(dgb + bgv);
                float ec = __expf(dgc + bgv);
                float wra = __fdividef(ea, 1.0f + __expf(-(dla + blv)));
                float wrb = __fdividef(eb, 1.0f + __expf(-(dlb + blv)));
                float wrc = __fdividef(ec, 1.0f + __expf(-(dlc + blv)));
                zacc += ea + eb + ec;
                wacc += wra + wrb + wrc;
                accum_pk(wra, xa0, xa1, s1p, s2p);
                accum_pk(wrb, xb0, xb1, s1p, s2p);
                accum_pk(wrc, xc0, xc1, s1p, s2p);
            } else {
                // ---- slow path: boundary/partial chunk ----
#pragma unroll
                for (int j = 0; j < RPW; j++) {
                    if (j < rv) {
                        int sv = __ldg(&seg[r0 + j]);
                        if (sv != cur) {
                            if (cur >= 0) flush_acc(cur, lane, s1p, s2p, zacc, wacc);
#pragma unroll
                            for (int k = 0; k < 4; k++) { s1p[k] = 0ull; s2p[k] = 0ull; }
                            zacc = 0.f; wacc = 0.f;
                            cur = sv;
                        }
                        const float* rp = tp + j * C + lane * 4;
                        ulonglong2 x0 = *(const ulonglong2*)(rp);
                        ulonglong2 x1 = *(const ulonglong2*)(rp + 128);
                        float dl = dot_pk(x0, x1, wl0, wl1);
                        float dg = dot_pk(x0, x1, wg0, wg1);
#pragma unroll
                        for (int o = 16; o; o >>= 1) {
                            dl += __shfl_xor_sync(0xffffffffu, dl, o);
                            dg += __shfl_xor_sync(0xffffffffu, dg, o);
                        }
                        float e  = __expf(dg + bgv);
                        float wr = __fdividef(e, 1.0f + __expf(-(dl + blv)));
                        zacc += e;
                        wacc += wr;
                        accum_pk(wr, x0, x1, s1p, s2p);
                    }
                }
            }
        }

        __syncwarp();   // all lanes done reading stage st
        if (lane == 0 && i + DEPTH < nt) {
            int r0n = (t0 + i + DEPTH) * TILE + warp * RPW;
            int rvn = min(RPW, n - r0n);
            if (rvn > 0) {
                uint32_t bytes = (uint32_t)rvn * C * 4;
                mbar_expect_tx(mb[st], bytes);
                bulk_g2s(buf_s[st], feats + (size_t)r0n * C, bytes, mb[st]);
            } else {
                mbar_arrive(mb[st]);
            }
        }
    }
    if (cur >= 0) flush_acc(cur, lane, s1p, s2p, zacc, wacc);
}

// ---------------------------------------------------------------------------
// finalize: fold 16 segments into mean/rstd, then re-zero accumulators
// ---------------------------------------------------------------------------
__global__ void finalize_kernel() {
    __shared__ float invZ[B];
    __shared__ float invU;
    int t = threadIdx.x;
    if (t < B) invZ[t] = 1.0f / g_Z[t];
    __syncthreads();
    if (t == 0) {
        float U = 0.f;
        for (int b = 0; b < B; b++) U += g_W[b] * invZ[b];
        invU = 1.0f / U;
    }
    __syncthreads();
    float m1 = 0.f, m2 = 0.f;
    for (int b = 0; b < B; b++) {
        m1 += g_S1[b * C + t] * invZ[b];
        m2 += g_S2[b * C + t] * invZ[b];
    }
    float iu = invU;
    m1 *= iu;
    m2 *= iu;
    float var = m2 - m1 * m1;   // sum(weight) == 1 exactly in the math
    g_mean[t] = m1;
    g_rstd[t] = 1.0f / sqrtf(var);
    for (int b = 0; b < B; b++) {
        g_S1[b * C + t] = 0.f;
        g_S2[b * C + t] = 0.f;
    }
    if (t < B) { g_Z[t] = 0.f; g_W[t] = 0.f; }
}

// ---------------------------------------------------------------------------
// pass 2: out = (x - mean[c]) * rstd[c]
// ---------------------------------------------------------------------------
__global__ __launch_bounds__(256)
void normalize_kernel(const float* __restrict__ feats,
                      float* __restrict__ out, int total4)
{
    int base = blockIdx.x * 1024 + threadIdx.x;
    if (base >= total4) return;
    const float4* f4 = (const float4*)feats;
    float4*       o4 = (float4*)out;
    const float4* m4 = (const float4*)g_mean;
    const float4* r4 = (const float4*)g_rstd;

    int cf = base & 63;
    float4 m  = m4[cf];
    float4 rs = r4[cf];

#pragma unroll
    for (int k = 0; k < 4; k++) {
        int i = base + k * 256;
        if (i < total4) {
            float4 x = __ldcs(f4 + i);
            float4 y;
            y.x = (x.x - m.x) * rs.x;
            y.y = (x.y - m.y) * rs.y;
            y.z = (x.z - m.z) * rs.z;
            y.w = (x.w - m.w) * rs.w;
            __stcs(o4 + i, y);
        }
    }
}

// ---------------------------------------------------------------------------
extern "C" void kernel_launch(void* const* d_in, const int* in_sizes, int n_in,
                              void* d_out, int out_size) {
    const float* feats = (const float*)d_in[0];
    const int*   seg   = (const int*)  d_in[1];
    const float* wl    = (const float*)d_in[2];
    const float* bl    = (const float*)d_in[3];
    const float* wg    = (const float*)d_in[4];
    const float* bg    = (const float*)d_in[5];
    float*       out   = (float*)d_out;

    int n = in_sizes[0] / C;

    cudaFuncSetAttribute(pass1_kernel,
                         cudaFuncAttributeMaxDynamicSharedMemorySize, SMEM_BYTES);

    pass1_kernel<<<NBLOCKS, THREADS, SMEM_BYTES>>>(feats, seg, wl, bl, wg, bg, n);

    finalize_kernel<<<1, C>>>();

    int total4 = n * (C / 4);
    normalize_kernel<<<(total4 + 1023) / 1024, 256>>>(feats, out, total4);
}

// round 17
// speedup vs baseline: 1.1981x; 1.0255x over previous
#include <cuda_runtime.h>
#include <math.h>
#include <stdint.h>

#define C 256
#define B 16
#define TILE 24              // rows per logical tile; 3 rows per warp
#define RPW 3                // rows per warp-chunk (3 KB)
#define DEPTH 3              // per-warp pipeline stages
#define NWARPS 8
#define THREADS 256
#define NBLOCKS 444          // 3 per SM

#define CHUNK_FLOATS (RPW * C)                    // 768 floats = 3 KB
#define WARP_BUF_FLOATS (DEPTH * CHUNK_FLOATS)    // 9 KB / warp
#define DATA_FLOATS (NWARPS * WARP_BUF_FLOATS)    // 72 KB / CTA
#define SMEM_BYTES (DATA_FLOATS * 4 + NWARPS * DEPTH * 8 + 16)

typedef unsigned long long u64t;

// Scratch accumulators (device globals; re-zeroed in finalize each replay)
__device__ float g_S1[B * C];
__device__ float g_S2[B * C];
__device__ float g_Z[B];
__device__ float g_W[B];
__device__ float g_mean[C];
__device__ float g_rstd[C];

// ---------------------------------------------------------------------------
// PTX helpers
// ---------------------------------------------------------------------------
__device__ __forceinline__ uint32_t smem_u32(const void* p) {
    uint32_t a;
    asm("{ .reg .u64 t; cvta.to.shared.u64 t, %1; cvt.u32.u64 %0, t; }"
        : "=r"(a) : "l"(p));
    return a;
}
__device__ __forceinline__ void mbar_init(uint32_t mbar, uint32_t cnt) {
    asm volatile("mbarrier.init.shared.b64 [%0], %1;" :: "r"(mbar), "r"(cnt) : "memory");
}
__device__ __forceinline__ void mbar_expect_tx(uint32_t mbar, uint32_t bytes) {
    asm volatile("mbarrier.arrive.expect_tx.shared.b64 _, [%0], %1;"
                 :: "r"(mbar), "r"(bytes) : "memory");
}
__device__ __forceinline__ void mbar_arrive(uint32_t mbar) {
    asm volatile("mbarrier.arrive.shared.b64 _, [%0];" :: "r"(mbar) : "memory");
}
__device__ __forceinline__ void bulk_g2s(uint32_t dst, const void* src,
                                         uint32_t bytes, uint32_t mbar) {
    asm volatile(
        "cp.async.bulk.shared::cta.global.mbarrier::complete_tx::bytes [%0], [%1], %2, [%3];"
        :: "r"(dst), "l"(src), "r"(bytes), "r"(mbar) : "memory");
}
__device__ __forceinline__ void mbar_wait(uint32_t mbar, uint32_t parity) {
    uint32_t done;
    asm volatile(
        "{\n\t.reg .pred p;\n\t"
        "mbarrier.try_wait.parity.acquire.cta.shared::cta.b64 p, [%1], %2;\n\t"
        "selp.b32 %0, 1, 0, p;\n\t}"
        : "=r"(done) : "r"(mbar), "r"(parity) : "memory");
    if (!done) {
        asm volatile(
            "{\n\t.reg .pred P1;\n\t"
            "W_%=:\n\t"
            "mbarrier.try_wait.parity.acquire.cta.shared::cta.b64 P1, [%0], %1, 0x989680;\n\t"
            "@P1 bra.uni D_%=;\n\t"
            "bra.uni W_%=;\n\t"
            "D_%=:\n\t}"
            :: "r"(mbar), "r"(parity) : "memory");
    }
}

// ---- packed f32x2 math ----------------------------------------------------
__device__ __forceinline__ u64t fma2(u64t a, u64t b, u64t c) {
    u64t d;
    asm("fma.rn.f32x2 %0, %1, %2, %3;" : "=l"(d) : "l"(a), "l"(b), "l"(c));
    return d;
}
__device__ __forceinline__ u64t mul2(u64t a, u64t b) {
    u64t d;
    asm("mul.rn.f32x2 %0, %1, %2;" : "=l"(d) : "l"(a), "l"(b));
    return d;
}
__device__ __forceinline__ u64t pk2(float lo, float hi) {
    u64t r;
    asm("mov.b64 %0, {%1, %2};" : "=l"(r) : "f"(lo), "f"(hi));
    return r;
}
__device__ __forceinline__ float2 upk2(u64t v) {
    float2 f;
    asm("mov.b64 {%0, %1}, %2;" : "=f"(f.x), "=f"(f.y) : "l"(v));
    return f;
}

// ---------------------------------------------------------------------------
__device__ __forceinline__ void flush_acc(int segv, int lane,
                                          u64t* s1p, u64t* s2p,
                                          float zacc, float wacc) {
    int c0 = lane * 4;
    int c1 = 128 + lane * 4;
    float2 v;
    v = upk2(s1p[0]); atomicAdd(&g_S1[segv*C + c0    ], v.x); atomicAdd(&g_S1[segv*C + c0 + 1], v.y);
    v = upk2(s1p[1]); atomicAdd(&g_S1[segv*C + c0 + 2], v.x); atomicAdd(&g_S1[segv*C + c0 + 3], v.y);
    v = upk2(s1p[2]); atomicAdd(&g_S1[segv*C + c1    ], v.x); atomicAdd(&g_S1[segv*C + c1 + 1], v.y);
    v = upk2(s1p[3]); atomicAdd(&g_S1[segv*C + c1 + 2], v.x); atomicAdd(&g_S1[segv*C + c1 + 3], v.y);
    v = upk2(s2p[0]); atomicAdd(&g_S2[segv*C + c0    ], v.x); atomicAdd(&g_S2[segv*C + c0 + 1], v.y);
    v = upk2(s2p[1]); atomicAdd(&g_S2[segv*C + c0 + 2], v.x); atomicAdd(&g_S2[segv*C + c0 + 3], v.y);
    v = upk2(s2p[2]); atomicAdd(&g_S2[segv*C + c1    ], v.x); atomicAdd(&g_S2[segv*C + c1 + 1], v.y);
    v = upk2(s2p[3]); atomicAdd(&g_S2[segv*C + c1 + 2], v.x); atomicAdd(&g_S2[segv*C + c1 + 3], v.y);
    if (lane == 0) {
        atomicAdd(&g_Z[segv], zacc);
        atomicAdd(&g_W[segv], wacc);
    }
}

// packed dot: 8 channels (4 pairs), two 2-deep chains for ILP
__device__ __forceinline__ float dot_pk(ulonglong2 a0, ulonglong2 a1,
                                        ulonglong2 w0, ulonglong2 w1) {
    u64t p = fma2(a0.x, w0.x, mul2(a0.y, w0.y));
    u64t q = fma2(a1.x, w1.x, mul2(a1.y, w1.y));
    float2 fp = upk2(p), fq = upk2(q);
    return (fp.x + fq.x) + (fp.y + fq.y);
}
// packed moment accumulation for one row (8 channels)
__device__ __forceinline__ void accum_pk(float wr, ulonglong2 a0, ulonglong2 a1,
                                         u64t* s1p, u64t* s2p) {
    u64t wr2 = pk2(wr, wr);
    s1p[0] = fma2(wr2, a0.x, s1p[0]);
    s1p[1] = fma2(wr2, a0.y, s1p[1]);
    s1p[2] = fma2(wr2, a1.x, s1p[2]);
    s1p[3] = fma2(wr2, a1.y, s1p[3]);
    s2p[0] = fma2(wr2, mul2(a0.x, a0.x), s2p[0]);
    s2p[1] = fma2(wr2, mul2(a0.y, a0.y), s2p[1]);
    s2p[2] = fma2(wr2, mul2(a1.x, a1.x), s2p[2]);
    s2p[3] = fma2(wr2, mul2(a1.y, a1.y), s2p[3]);
}

// ---------------------------------------------------------------------------
// pass 1: PER-WARP private TMA pipelines (R13 optimum: RPW=3, DEPTH=3, 3/SM).
// ---------------------------------------------------------------------------
extern __shared__ char smem_raw[];

__global__ __launch_bounds__(THREADS, 3)
void pass1_kernel(const float* __restrict__ feats,
                  const int*   __restrict__ seg,
                  const float* __restrict__ wl,
                  const float* __restrict__ bl,
                  const float* __restrict__ wg,
                  const float* __restrict__ bg,
                  int n)
{
    __shared__ float4 swl[64];
    __shared__ float4 swg[64];

    float* data = (float*)smem_raw;
    uint64_t* mbar64 = (uint64_t*)(smem_raw + (size_t)DATA_FLOATS * 4);

    int ntiles = (n + TILE - 1) / TILE;
    int chunk  = (ntiles + NBLOCKS - 1) / NBLOCKS;
    int t0 = blockIdx.x * chunk;
    int t1 = min(ntiles, t0 + chunk);
    int nt = t1 - t0;

    int tid  = threadIdx.x;
    int warp = tid >> 5;
    int lane = tid & 31;

    // weights preload
    if (tid < 64)        swl[tid]      = ((const float4*)wl)[tid];
    else if (tid < 128)  swg[tid - 64] = ((const float4*)wg)[tid - 64];

    // this warp's private ring
    float* wbuf = data + warp * WARP_BUF_FLOATS;
    uint32_t mb[DEPTH], buf_s[DEPTH];
#pragma unroll
    for (int d = 0; d < DEPTH; d++) {
        mb[d]    = smem_u32(&mbar64[warp * DEPTH + d]);
        buf_s[d] = smem_u32(wbuf + d * CHUNK_FLOATS);
    }
    if (lane == 0) {
#pragma unroll
        for (int d = 0; d < DEPTH; d++) mbar_init(mb[d], 1);
    }
    __syncthreads();   // weights visible; warp-local mbars ready

    if (nt <= 0) return;

    // prologue: this warp issues its first DEPTH chunks
    if (lane == 0) {
#pragma unroll
        for (int d = 0; d < DEPTH; d++) {
            if (d < nt) {
                int r0 = (t0 + d) * TILE + warp * RPW;
                int rv = min(RPW, n - r0);
                if (rv > 0) {
                    uint32_t bytes = (uint32_t)rv * C * 4;
                    mbar_expect_tx(mb[d], bytes);
                    bulk_g2s(buf_s[d], feats + (size_t)r0 * C, bytes, mb[d]);
                } else {
                    mbar_arrive(mb[d]);
                }
            } else {
                mbar_arrive(mb[d]);
            }
        }
    }

    float blv = bl[0], bgv = bg[0];

    u64t s1p[4], s2p[4];
#pragma unroll
    for (int k = 0; k < 4; k++) { s1p[k] = 0ull; s2p[k] = 0ull; }
    float zacc = 0.f, wacc = 0.f;
    int cur = -1;

    ulonglong2 wl0 = *(const ulonglong2*)&swl[lane];
    ulonglong2 wl1 = *(const ulonglong2*)&swl[32 + lane];
    ulonglong2 wg0 = *(const ulonglong2*)&swg[lane];
    ulonglong2 wg1 = *(const ulonglong2*)&swg[32 + lane];

    for (int i = 0; i < nt; i++) {
        int st = i % DEPTH;
        uint32_t parity = (uint32_t)((i / DEPTH) & 1);
        mbar_wait(mb[st], parity);

        int r0 = (t0 + i) * TILE + warp * RPW;
        int rv = min(RPW, n - r0);

        if (rv > 0) {
            const float* tp = wbuf + st * CHUNK_FLOATS;
            int s_lo = __ldg(&seg[r0]);
            int s_hi = __ldg(&seg[r0 + rv - 1]);

            if (s_lo == s_hi && rv == RPW) {
                // ---- fast path: 3 rows, one segment ----
                if (s_lo != cur) {
                    if (cur >= 0) flush_acc(cur, lane, s1p, s2p, zacc, wacc);
#pragma unroll
                    for (int k = 0; k < 4; k++) { s1p[k] = 0ull; s2p[k] = 0ull; }
                    zacc = 0.f; wacc = 0.f;
                    cur = s_lo;
                }
                const float* rp = tp + lane * 4;
                ulonglong2 xa0 = *(const ulonglong2*)(rp);
                ulonglong2 xa1 = *(const ulonglong2*)(rp + 128);
                ulonglong2 xb0 = *(const ulonglong2*)(rp + C);
                ulonglong2 xb1 = *(const ulonglong2*)(rp + C + 128);
                ulonglong2 xc0 = *(const ulonglong2*)(rp + 2 * C);
                ulonglong2 xc1 = *(const ulonglong2*)(rp + 2 * C + 128);

                float dla = dot_pk(xa0, xa1, wl0, wl1), dga = dot_pk(xa0, xa1, wg0, wg1);
                float dlb = dot_pk(xb0, xb1, wl0, wl1), dgb = dot_pk(xb0, xb1, wg0, wg1);
                float dlc = dot_pk(xc0, xc1, wl0, wl1), dgc = dot_pk(xc0, xc1, wg0, wg1);

                // 6 interleaved butterfly chains
#pragma unroll
                for (int o = 16; o; o >>= 1) {
                    dla += __shfl_xor_sync(0xffffffffu, dla, o);
                    dga += __shfl_xor_sync(0xffffffffu, dga, o);
                    dlb += __shfl_xor_sync(0xffffffffu, dlb, o);
                    dgb += __shfl_xor_sync(0xffffffffu, dgb, o);
                    dlc += __shfl_xor_sync(0xffffffffu, dlc, o);
                    dgc += __shfl_xor_sync(0xffffffffu, dgc, o);
                }
                float ea = __expf(dga + bgv);
                float eb = __expf(dgb + bgv);
                float ec = __expf(dgc + bgv);
                float wra = __fdividef(ea, 1.0f + __expf(-(dla + blv)));
                float wrb = __fdividef(eb, 1.0f + __expf(-(dlb + blv)));
                float wrc = __fdividef(ec, 1.0f + __expf(-(dlc + blv)));
                zacc += ea + eb + ec;
                wacc += wra + wrb + wrc;
                accum_pk(wra, xa0, xa1, s1p, s2p);
                accum_pk(wrb, xb0, xb1, s1p, s2p);
                accum_pk(wrc, xc0, xc1, s1p, s2p);
            } else {
                // ---- slow path: boundary/partial chunk ----
#pragma unroll
                for (int j = 0; j < RPW; j++) {
                    if (j < rv) {
                        int sv = __ldg(&seg[r0 + j]);
                        if (sv != cur) {
                            if (cur >= 0) flush_acc(cur, lane, s1p, s2p, zacc, wacc);
#pragma unroll
                            for (int k = 0; k < 4; k++) { s1p[k] = 0ull; s2p[k] = 0ull; }
                            zacc = 0.f; wacc = 0.f;
                            cur = sv;
                        }
                        const float* rp = tp + j * C + lane * 4;
                        ulonglong2 x0 = *(const ulonglong2*)(rp);
                        ulonglong2 x1 = *(const ulonglong2*)(rp + 128);
                        float dl = dot_pk(x0, x1, wl0, wl1);
                        float dg = dot_pk(x0, x1, wg0, wg1);
#pragma unroll
                        for (int o = 16; o; o >>= 1) {
                            dl += __shfl_xor_sync(0xffffffffu, dl, o);
                            dg += __shfl_xor_sync(0xffffffffu, dg, o);
                        }
                        float e  = __expf(dg + bgv);
                        float wr = __fdividef(e, 1.0f + __expf(-(dl + blv)));
                        zacc += e;
                        wacc += wr;
                        accum_pk(wr, x0, x1, s1p, s2p);
                    }
                }
            }
        }

        __syncwarp();   // all lanes done reading stage st
        if (lane == 0 && i + DEPTH < nt) {
            int r0n = (t0 + i + DEPTH) * TILE + warp * RPW;
            int rvn = min(RPW, n - r0n);
            if (rvn > 0) {
                uint32_t bytes = (uint32_t)rvn * C * 4;
                mbar_expect_tx(mb[st], bytes);
                bulk_g2s(buf_s[st], feats + (size_t)r0n * C, bytes, mb[st]);
            } else {
                mbar_arrive(mb[st]);
            }
        }
    }
    if (cur >= 0) flush_acc(cur, lane, s1p, s2p, zacc, wacc);
}

// ---------------------------------------------------------------------------
// finalize: fold 16 segments into mean/rstd, then re-zero accumulators
// ---------------------------------------------------------------------------
__global__ void finalize_kernel() {
    __shared__ float invZ[B];
    __shared__ float invU;
    int t = threadIdx.x;
    if (t < B) invZ[t] = 1.0f / g_Z[t];
    __syncthreads();
    if (t == 0) {
        float U = 0.f;
        for (int b = 0; b < B; b++) U += g_W[b] * invZ[b];
        invU = 1.0f / U;
    }
    __syncthreads();
    float m1 = 0.f, m2 = 0.f;
    for (int b = 0; b < B; b++) {
        m1 += g_S1[b * C + t] * invZ[b];
        m2 += g_S2[b * C + t] * invZ[b];
    }
    float iu = invU;
    m1 *= iu;
    m2 *= iu;
    float var = m2 - m1 * m1;   // sum(weight) == 1 exactly in the math
    g_mean[t] = m1;
    g_rstd[t] = 1.0f / sqrtf(var);
    for (int b = 0; b < B; b++) {
        g_S1[b * C + t] = 0.f;
        g_S2[b * C + t] = 0.f;
    }
    if (t < B) { g_Z[t] = 0.f; g_W[t] = 0.f; }
}

// ---------------------------------------------------------------------------
// pass 2: out = (x - mean[c]) * rstd[c].
// REVERSED block order: earliest-scheduled blocks read the TAIL of feats,
// which is still resident in L2 from pass1's streaming read (~120 MB).
// ---------------------------------------------------------------------------
__global__ __launch_bounds__(256)
void normalize_kernel(const float* __restrict__ feats,
                      float* __restrict__ out, int total4)
{
    int blk  = gridDim.x - 1 - blockIdx.x;   // reverse: first blocks -> tail
    int base = blk * 1024 + threadIdx.x;
    if (base >= total4) return;
    const float4* f4 = (const float4*)feats;
    float4*       o4 = (float4*)out;
    const float4* m4 = (const float4*)g_mean;
    const float4* r4 = (const float4*)g_rstd;

    int cf = base & 63;
    float4 m  = m4[cf];
    float4 rs = r4[cf];

#pragma unroll
    for (int k = 0; k < 4; k++) {
        int i = base + k * 256;
        if (i < total4) {
            float4 x = __ldcs(f4 + i);
            float4 y;
            y.x = (x.x - m.x) * rs.x;
            y.y = (x.y - m.y) * rs.y;
            y.z = (x.z - m.z) * rs.z;
            y.w = (x.w - m.w) * rs.w;
            __stcs(o4 + i, y);
        }
    }
}

// ---------------------------------------------------------------------------
extern "C" void kernel_launch(void* const* d_in, const int* in_sizes, int n_in,
                              void* d_out, int out_size) {
    const float* feats = (const float*)d_in[0];
    const int*   seg   = (const int*)  d_in[1];
    const float* wl    = (const float*)d_in[2];
    const float* bl    = (const float*)d_in[3];
    const float* wg    = (const float*)d_in[4];
    const float* bg    = (const float*)d_in[5];
    float*       out   = (float*)d_out;

    int n = in_sizes[0] / C;

    cudaFuncSetAttribute(pass1_kernel,
                         cudaFuncAttributeMaxDynamicSharedMemorySize, SMEM_BYTES);

    pass1_kernel<<<NBLOCKS, THREADS, SMEM_BYTES>>>(feats, seg, wl, bl, wg, bg, n);

    finalize_kernel<<<1, C>>>();

    int total4 = n * (C / 4);
    normalize_kernel<<<(total4 + 1023) / 1024, 256>>>(feats, out, total4);
}